// round 12
// baseline (speedup 1.0000x reference)
#include <cuda_runtime.h>
#include <cstdint>
#include <float.h>

#define Nn    4096
#define NMASK 4095
#define Hh    64
#define KNN   15
#define MAXE  65536
#define NK    (Nn*KNN)
#define XMAX  (MAXE+NK)
#define CAND  160
#define U64MAX 0xFFFFFFFFFFFFFFFFULL

// ---------------- scratch (device globals; no allocs) ----------------
__device__ int      g_is64;
__device__ float4   g_pts[Nn];                  // x,y,z,|x|^2
__device__ float    g_y[Nn*Hh];
__device__ float    g_minv[Nn*Hh];
__device__ float    g_feats[Nn*Hh];
__device__ float    g_q[Nn*Hh];
__device__ float    g_k[Nn*Hh];
__device__ int      g_knn[NK];
__device__ float    g_attn[MAXE];
__device__ unsigned g_rowmaxkey[Nn];
__device__ float    g_rowsum[Nn];
__device__ int      g_rowcnt[Nn];
__device__ int      g_colcnt[Nn];
__device__ int      g_rowptr[Nn+1];
__device__ int      g_colptr[Nn+1];
__device__ int      g_rowfill[Nn];
__device__ int      g_colfill[Nn];
__device__ int      g_xfill[Nn];
__device__ int      g_xcols[XMAX];
__device__ unsigned long long g_rowpack[MAXE];  // (f32bits(val)<<32)|col  CSR of S
__device__ unsigned long long g_cscpack[MAXE];  // (f32bits(val)<<32)|row  CSC of S

// ---------------- helpers ----------------
__device__ __forceinline__ unsigned fenc(float f) {
    unsigned u = __float_as_uint(f);
    return (u & 0x80000000u) ? ~u : (u ^ 0x80000000u);
}
__device__ __forceinline__ float fdec(unsigned e) {
    unsigned u = (e & 0x80000000u) ? (e ^ 0x80000000u) : ~e;
    return __uint_as_float(u);
}
__device__ __forceinline__ void edge_rc(const long long* e64, const int* e32,
                                        int E, int is64, int e, int& r, int& c) {
    if (is64) { r = ((int)e64[e]) & NMASK; c = ((int)e64[E + e]) & NMASK; }
    else      { r = e32[e] & NMASK;        c = e32[E + e] & NMASK; }
}
__device__ __forceinline__ unsigned long long umin64(unsigned long long a,
                                                     unsigned long long b) {
    return a < b ? a : b;
}

// ---------------- kernels ----------------
// detect dtype (thread 0) + init per-node state (merged; saves one launch)
__global__ void k_initdetect(const unsigned long long* ei) {
    int t = blockIdx.x * blockDim.x + threadIdx.x;
    if (t == 0) {
        int ok64 = 1;
        for (int i = 0; i < 64; ++i) {
            unsigned long long v = ei[i];
            if ((v >> 32) != 0ULL || (v & 0xFFFFFFFFULL) >= (unsigned)Nn) { ok64 = 0; break; }
        }
        g_is64 = ok64;
    }
    if (t < Nn) {
        g_rowmaxkey[t] = 0u;
        g_rowsum[t] = 0.0f;
        g_rowcnt[t] = 0;
        g_colcnt[t] = 0;
    }
}

// y = x @ W_theta^T (bias folded later); also build g_pts
__global__ void k_y(const float* __restrict__ x, const float* __restrict__ Wt) {
    int t = blockIdx.x * blockDim.x + threadIdx.x;
    if (t >= Nn * Hh) return;
    int i = t >> 6, f = t & 63;
    float x0 = x[i*3+0], x1 = x[i*3+1], x2 = x[i*3+2];
    g_y[t] = Wt[f*3+0]*x0 + Wt[f*3+1]*x1 + Wt[f*3+2]*x2;
    if (f == 0) g_pts[i] = make_float4(x0, x1, x2, x0*x0 + x1*x1 + x2*x2);
}

// kNN v6: 512 threads/block (8 pts each, d2v[8] -> fewer regs, ~100% occ).
// T = 15th smallest of 512 per-thread minima (provable upper bound on true
// 15th-NN d2, tighter than with 256). Candidates <= T exact-selected with
// (fenc(d2),j) keys (JAX tie order).
__global__ void k_knn() {
    __shared__ float smin[512];
    __shared__ unsigned long long scand[CAND];
    __shared__ int scnt;
    __shared__ float sT;
    int i = blockIdx.x, t = threadIdx.x;

    float4 Q = g_pts[i];
    float d2v[8];
    float m = FLT_MAX;
    #pragma unroll
    for (int u = 0; u < 8; ++u) {
        int j = u*512 + t;
        float4 P = g_pts[j];
        float dot = Q.x*P.x + Q.y*P.y + Q.z*P.z;
        float d2  = (Q.w - 2.0f*dot) + P.w;     // matches (sq_i - 2*xy) + sq_j
        if (j == i) d2 = FLT_MAX;
        d2v[u] = d2;
        m = fminf(m, d2);
    }
    smin[t] = m;
    if (t == 0) scnt = 0;
    __syncthreads();

    if (t < 32) {
        unsigned long long v[16];
        #pragma unroll
        for (int u = 0; u < 16; ++u) {
            int idx = u*32 + t;
            v[u] = ((unsigned long long)fenc(smin[idx]) << 32) | (unsigned)idx;
        }
        unsigned long long last = 0;
        for (int r = 0; r < KNN; ++r) {
            unsigned long long mm = U64MAX;
            #pragma unroll
            for (int u = 0; u < 16; ++u) mm = umin64(mm, v[u]);
            #pragma unroll
            for (int o = 16; o; o >>= 1) {
                unsigned long long s = __shfl_xor_sync(0xffffffffu, mm, o);
                mm = umin64(mm, s);
            }
            #pragma unroll
            for (int u = 0; u < 16; ++u) if (v[u] == mm) v[u] = U64MAX;
            last = mm;
        }
        if (t == 0) sT = fdec((unsigned)(last >> 32));
    }
    __syncthreads();

    float T = sT;
    #pragma unroll
    for (int u = 0; u < 8; ++u) {
        if (d2v[u] <= T) {
            int p = atomicAdd(&scnt, 1);
            if (p < CAND)
                scand[p] = ((unsigned long long)fenc(d2v[u]) << 32) | (unsigned)(u*512 + t);
        }
    }
    __syncthreads();

    int cnt = scnt; if (cnt > CAND) cnt = CAND;
    if (cnt == KNN) {
        if (t < KNN) g_knn[i*KNN + t] = (int)(scand[t] & 0xFFFFFFFFu);
    } else if (t < 32) {
        unsigned long long v[5];
        #pragma unroll
        for (int u = 0; u < 5; ++u) {
            int idx = u*32 + t;
            v[u] = (idx < cnt) ? scand[idx] : U64MAX;
        }
        for (int r = 0; r < KNN; ++r) {
            unsigned long long mm = U64MAX;
            #pragma unroll
            for (int u = 0; u < 5; ++u) mm = umin64(mm, v[u]);
            #pragma unroll
            for (int o = 16; o; o >>= 1) {
                unsigned long long s = __shfl_xor_sync(0xffffffffu, mm, o);
                mm = umin64(mm, s);
            }
            #pragma unroll
            for (int u = 0; u < 5; ++u) if (v[u] == mm) v[u] = U64MAX;
            if (t == 0) g_knn[i*KNN + r] = (int)(mm & 0xFFFFFFFFu);
        }
    }
}

// count original edges per row/col (for CSR/CSC of S)
__global__ void k_count(const long long* __restrict__ e64,
                        const int* __restrict__ e32, int E) {
    int is64 = g_is64;
    int e = blockIdx.x * blockDim.x + threadIdx.x;
    if (e >= E) return;
    int r, c; edge_rc(e64, e32, E, is64, e, r, c);
    atomicAdd(&g_rowcnt[r], 1);
    atomicAdd(&g_colcnt[c], 1);
}

// exclusive scan: block 0 rows (+xfill = rowptr + 15*i), block 1 cols
__global__ void k_scan() {
    int isrow = (blockIdx.x == 0);
    const int* cnt = isrow ? g_rowcnt : g_colcnt;
    int* ptr  = isrow ? g_rowptr  : g_colptr;
    int* fill = isrow ? g_rowfill : g_colfill;
    __shared__ int sh[1024];
    int t = threadIdx.x;
    int v[4]; int s = 0;
    #pragma unroll
    for (int k = 0; k < 4; ++k) { v[k] = cnt[t*4 + k]; s += v[k]; }
    sh[t] = s;
    __syncthreads();
    for (int d = 1; d < 1024; d <<= 1) {
        int add = (t >= d) ? sh[t - d] : 0;
        __syncthreads();
        sh[t] += add;
        __syncthreads();
    }
    int excl = sh[t] - s;
    #pragma unroll
    for (int k = 0; k < 4; ++k) {
        int idx = t*4 + k;
        ptr[idx] = excl; fill[idx] = excl;
        if (isrow) g_xfill[idx] = excl + KNN*idx;
        excl += v[k];
    }
    if (t == 1023) ptr[Nn] = excl;
}

// scatter extended adjacency (orig edges + kNN) into xcols
__global__ void k_xscatter(const long long* __restrict__ e64,
                           const int* __restrict__ e32, int E) {
    int is64 = g_is64;
    int t = blockIdx.x * blockDim.x + threadIdx.x;
    if (t < E) {
        int r, c; edge_rc(e64, e32, E, is64, t, r, c);
        int p = atomicAdd(&g_xfill[r], 1);
        g_xcols[p] = c;
    } else if (t < E + NK) {
        int ke = t - E;
        int r = ke / KNN;
        int p = atomicAdd(&g_xfill[r], 1);
        g_xcols[p] = g_knn[ke] & NMASK;
    }
}

// per-node per-feature min of y over extended neighbors (gather, no atomics)
__global__ void k_min() {
    __shared__ float red[256];
    int i = blockIdx.x, t = threadIdx.x;
    int f = t & 63, c = t >> 6;
    int x0 = g_rowptr[i]   + KNN * i;
    int x1 = g_rowptr[i+1] + KNN * (i+1);
    float m = FLT_MAX;
    for (int p = x0 + c; p < x1; p += 4) {
        int col = g_xcols[p];
        m = fminf(m, g_y[col*Hh + f]);
    }
    red[t] = m;
    __syncthreads();
    if (t < 128) red[t] = fminf(red[t], red[t + 128]);
    __syncthreads();
    if (t < 64) g_minv[i*Hh + t] = fminf(red[t], red[t + 64]);
}

// feats = (y + b_theta - min) @ W_phi^T + b_phi      (32 rows/block)
__global__ void k_feats(const float* __restrict__ bth,
                        const float* __restrict__ Wphi,
                        const float* __restrict__ bphi) {
    __shared__ float sWt[Hh*Hh];
    __shared__ float sA[32*Hh];
    int t = threadIdx.x;
    int r0 = blockIdx.x * 32;
    for (int idx = t; idx < Hh*Hh; idx += 256) {
        int f = idx >> 6, h = idx & 63;
        sWt[h*Hh + f] = Wphi[idx];
    }
    for (int idx = t; idx < 32*Hh; idx += 256) {
        int f = idx & 63;
        int gi = r0*Hh + idx;
        sA[idx] = g_y[gi] + bth[f] - g_minv[gi];
    }
    __syncthreads();
    for (int o = t; o < 32*Hh; o += 256) {
        int li = o >> 6, f = o & 63;
        float acc = bphi[f];
        #pragma unroll
        for (int h = 0; h < Hh; ++h) acc += sA[li*Hh + h] * sWt[h*Hh + f];
        g_feats[r0*Hh + o] = acc;
    }
}

// q = feats @ W_q^T,  k = feats @ W_k^T
__global__ void k_qk(const float* __restrict__ Wq, const float* __restrict__ Wk) {
    __shared__ float sWq[Hh*Hh];
    __shared__ float sWk[Hh*Hh];
    __shared__ float sF[32*Hh];
    int t = threadIdx.x;
    int r0 = blockIdx.x * 32;
    for (int idx = t; idx < Hh*Hh; idx += 256) {
        int f = idx >> 6, h = idx & 63;
        sWq[h*Hh + f] = Wq[idx];
        sWk[h*Hh + f] = Wk[idx];
    }
    for (int idx = t; idx < 32*Hh; idx += 256) sF[idx] = g_feats[r0*Hh + idx];
    __syncthreads();
    for (int o = t; o < 32*Hh; o += 256) {
        int li = o >> 6, f = o & 63;
        float aq = 0.0f, ak = 0.0f;
        #pragma unroll
        for (int h = 0; h < Hh; ++h) {
            float fv = sF[li*Hh + h];
            aq += fv * sWq[h*Hh + f];
            ak += fv * sWk[h*Hh + f];
        }
        g_q[r0*Hh + o] = aq;
        g_k[r0*Hh + o] = ak;
    }
}

// attn[e] = dot(q[row], k[col]); row-max via encoded atomicMax. warp/edge.
__global__ void k_attn(const long long* __restrict__ e64,
                       const int* __restrict__ e32, int E) {
    int is64 = g_is64;
    int w = (blockIdx.x * blockDim.x + threadIdx.x) >> 5;
    int lane = threadIdx.x & 31;
    if (w >= E) return;
    int row, col;
    edge_rc(e64, e32, E, is64, w, row, col);
    float a = g_q[row*Hh + lane]      * g_k[col*Hh + lane]
            + g_q[row*Hh + 32 + lane] * g_k[col*Hh + 32 + lane];
    #pragma unroll
    for (int o = 16; o; o >>= 1) a += __shfl_xor_sync(0xffffffffu, a, o);
    if (lane == 0) {
        g_attn[w] = a;
        atomicMax(&g_rowmaxkey[row], fenc(a));
    }
}

__global__ void k_exp(const long long* __restrict__ e64,
                      const int* __restrict__ e32, int E) {
    int is64 = g_is64;
    int e = blockIdx.x * blockDim.x + threadIdx.x;
    if (e >= E) return;
    int row, col;
    edge_rc(e64, e32, E, is64, e, row, col);
    float v = expf(g_attn[e] - fdec(g_rowmaxkey[row]));
    g_attn[e] = v;
    atomicAdd(&g_rowsum[row], v);
}

// normalize + scatter S into packed CSR and CSC (duplicates kept)
__global__ void k_sscatter(const long long* __restrict__ e64,
                           const int* __restrict__ e32, int E) {
    int is64 = g_is64;
    int e = blockIdx.x * blockDim.x + threadIdx.x;
    if (e >= E) return;
    int row, col;
    edge_rc(e64, e32, E, is64, e, row, col);
    float sc = g_attn[e] / g_rowsum[row];
    unsigned long long pv = ((unsigned long long)__float_as_uint(sc)) << 32;
    int p = atomicAdd(&g_rowfill[row], 1);
    g_rowpack[p] = pv | (unsigned)col;
    int c = atomicAdd(&g_colfill[col], 1);
    g_cscpack[c] = pv | (unsigned)row;
}

// A_s row i: 512 threads, warp per S-entry p, lane per A-entry qq (champion)
__global__ void k_out(float* __restrict__ out) {
    __shared__ float orow[Nn];   // 16 KB
    int i = blockIdx.x, t = threadIdx.x;
    int lane = t & 31, w = t >> 5;               // 16 warps
    for (int j = t; j < Nn; j += 512) orow[j] = 0.0f;
    __syncthreads();
    int r0 = g_rowptr[i], r1 = g_rowptr[i+1];
    for (int p = r0 + w; p < r1; p += 16) {
        unsigned long long pk = g_rowpack[p];
        int k = (int)(pk & 0xFFFFFFFFu);
        float s = __uint_as_float((unsigned)(pk >> 32));
        int a0 = g_rowptr[k], a1 = g_rowptr[k+1];
        for (int qq = a0 + lane; qq < a1; qq += 32) {
            int l = (int)(g_rowpack[qq] & 0xFFFFFFFFu);
            int c0 = g_colptr[l], c1 = g_colptr[l+1];
            for (int r = c0; r < c1; ++r) {
                unsigned long long ck = g_cscpack[r];
                atomicAdd(&orow[(unsigned)(ck & 0xFFFFFFFFu)],
                          s * __uint_as_float((unsigned)(ck >> 32)));
            }
        }
    }
    __syncthreads();
    float4* o4 = (float4*)(out + (size_t)i * Nn);
    for (int j = t; j < Nn/4; j += 512)
        o4[j] = make_float4(orow[4*j], orow[4*j+1], orow[4*j+2], orow[4*j+3]);
}

// ---------------- launch ----------------
extern "C" void kernel_launch(void* const* d_in, const int* in_sizes, int n_in,
                              void* d_out, int out_size) {
    const float* x    = (const float*)d_in[0];
    const void*  ei   = d_in[1];
    const float* Wth  = (const float*)d_in[2];
    const float* bth  = (const float*)d_in[3];
    const float* Wphi = (const float*)d_in[4];
    const float* bphi = (const float*)d_in[5];
    const float* Wq   = (const float*)d_in[6];
    const float* Wk   = (const float*)d_in[7];
    float* out = (float*)d_out;

    int E = in_sizes[1] / 2;
    const long long* e64 = (const long long*)ei;
    const int*       e32 = (const int*)ei;

    k_initdetect<<<16, 256>>>((const unsigned long long*)ei);
    k_y<<<(Nn*Hh + 255)/256, 256>>>(x, Wth);
    k_knn<<<Nn, 512>>>();
    k_count<<<(E + 255)/256, 256>>>(e64, e32, E);
    k_scan<<<2, 1024>>>();
    k_xscatter<<<(E + NK + 255)/256, 256>>>(e64, e32, E);
    k_min<<<Nn, 256>>>();
    k_feats<<<Nn/32, 256>>>(bth, Wphi, bphi);
    k_qk<<<Nn/32, 256>>>(Wq, Wk);
    k_attn<<<(E*32 + 255)/256, 256>>>(e64, e32, E);
    k_exp<<<(E + 255)/256, 256>>>(e64, e32, E);
    k_sscatter<<<(E + 255)/256, 256>>>(e64, e32, E);
    k_out<<<Nn, 512>>>(out);
}

// round 13
// speedup vs baseline: 1.1416x; 1.1416x over previous
#include <cuda_runtime.h>
#include <cstdint>
#include <float.h>

#define Nn    4096
#define NMASK 4095
#define Hh    64
#define KNN   15
#define MAXE  65536
#define NK    (Nn*KNN)
#define XMAX  (MAXE+NK)
#define CAND  160
#define U64MAX 0xFFFFFFFFFFFFFFFFULL

// ---------------- scratch (device globals; no allocs) ----------------
__device__ int      g_is64;
__device__ float4   g_pts[Nn];                  // x,y,z,|x|^2
__device__ float    g_y[Nn*Hh];
__device__ float    g_minv[Nn*Hh];
__device__ float    g_feats[Nn*Hh];
__device__ float    g_q[Nn*Hh];
__device__ float    g_k[Nn*Hh];
__device__ int      g_knn[NK];
__device__ int      g_rowcnt[Nn];
__device__ int      g_colcnt[Nn];
__device__ int      g_rowptr[Nn+1];
__device__ int      g_colptr[Nn+1];
__device__ int      g_rowfill[Nn];
__device__ int      g_colfill[Nn];
__device__ int      g_xfill[Nn];
__device__ int      g_xcols[XMAX];
__device__ unsigned long long g_rowpack[MAXE];  // (f32bits(val)<<32)|col  CSR of S
__device__ unsigned long long g_cscpack[MAXE];  // (f32bits(val)<<32)|row  CSC of S

// ---------------- helpers ----------------
__device__ __forceinline__ unsigned fenc(float f) {
    unsigned u = __float_as_uint(f);
    return (u & 0x80000000u) ? ~u : (u ^ 0x80000000u);
}
__device__ __forceinline__ float fdec(unsigned e) {
    unsigned u = (e & 0x80000000u) ? (e ^ 0x80000000u) : ~e;
    return __uint_as_float(u);
}
__device__ __forceinline__ void edge_rc(const long long* e64, const int* e32,
                                        int E, int is64, int e, int& r, int& c) {
    if (is64) { r = ((int)e64[e]) & NMASK; c = ((int)e64[E + e]) & NMASK; }
    else      { r = e32[e] & NMASK;        c = e32[E + e] & NMASK; }
}
__device__ __forceinline__ unsigned long long umin64(unsigned long long a,
                                                     unsigned long long b) {
    return a < b ? a : b;
}

// ---------------- kernels ----------------
// detect dtype (thread 0) + init per-node state (merged)
__global__ void k_initdetect(const unsigned long long* ei) {
    int t = blockIdx.x * blockDim.x + threadIdx.x;
    if (t == 0) {
        int ok64 = 1;
        for (int i = 0; i < 64; ++i) {
            unsigned long long v = ei[i];
            if ((v >> 32) != 0ULL || (v & 0xFFFFFFFFULL) >= (unsigned)Nn) { ok64 = 0; break; }
        }
        g_is64 = ok64;
    }
    if (t < Nn) {
        g_rowcnt[t] = 0;
        g_colcnt[t] = 0;
    }
}

// y = x @ W_theta^T (bias folded later); also build g_pts
__global__ void k_y(const float* __restrict__ x, const float* __restrict__ Wt) {
    int t = blockIdx.x * blockDim.x + threadIdx.x;
    if (t >= Nn * Hh) return;
    int i = t >> 6, f = t & 63;
    float x0 = x[i*3+0], x1 = x[i*3+1], x2 = x[i*3+2];
    g_y[t] = Wt[f*3+0]*x0 + Wt[f*3+1]*x1 + Wt[f*3+2]*x2;
    if (f == 0) g_pts[i] = make_float4(x0, x1, x2, x0*x0 + x1*x1 + x2*x2);
}

// kNN v5 (measured 42.5us): block per query, float4 loads, threshold-then-select.
// T = 15th smallest of 256 per-thread minima (provable upper bound on true
// 15th-NN d2). Candidates <= T exact-selected with (fenc(d2),j) keys (JAX ties).
__global__ void k_knn() {
    __shared__ float smin[256];
    __shared__ unsigned long long scand[CAND];
    __shared__ int scnt;
    __shared__ float sT;
    int i = blockIdx.x, t = threadIdx.x;

    float4 Q = g_pts[i];
    float d2v[16];
    float m = FLT_MAX;
    #pragma unroll
    for (int u = 0; u < 16; ++u) {
        int j = u*256 + t;
        float4 P = g_pts[j];
        float dot = Q.x*P.x + Q.y*P.y + Q.z*P.z;
        float d2  = (Q.w - 2.0f*dot) + P.w;     // matches (sq_i - 2*xy) + sq_j
        if (j == i) d2 = FLT_MAX;
        d2v[u] = d2;
        m = fminf(m, d2);
    }
    smin[t] = m;
    if (t == 0) scnt = 0;
    __syncthreads();

    if (t < 32) {
        unsigned long long v[8];
        #pragma unroll
        for (int u = 0; u < 8; ++u) {
            int idx = u*32 + t;
            v[u] = ((unsigned long long)fenc(smin[idx]) << 32) | (unsigned)idx;
        }
        unsigned long long last = 0;
        for (int r = 0; r < KNN; ++r) {
            unsigned long long mm = U64MAX;
            #pragma unroll
            for (int u = 0; u < 8; ++u) mm = umin64(mm, v[u]);
            #pragma unroll
            for (int o = 16; o; o >>= 1) {
                unsigned long long s = __shfl_xor_sync(0xffffffffu, mm, o);
                mm = umin64(mm, s);
            }
            #pragma unroll
            for (int u = 0; u < 8; ++u) if (v[u] == mm) v[u] = U64MAX;
            last = mm;
        }
        if (t == 0) sT = fdec((unsigned)(last >> 32));
    }
    __syncthreads();

    float T = sT;
    #pragma unroll
    for (int u = 0; u < 16; ++u) {
        if (d2v[u] <= T) {
            int p = atomicAdd(&scnt, 1);
            if (p < CAND)
                scand[p] = ((unsigned long long)fenc(d2v[u]) << 32) | (unsigned)(u*256 + t);
        }
    }
    __syncthreads();

    int cnt = scnt; if (cnt > CAND) cnt = CAND;
    if (cnt == KNN) {
        if (t < KNN) g_knn[i*KNN + t] = (int)(scand[t] & 0xFFFFFFFFu);
    } else if (t < 32) {
        unsigned long long v[5];
        #pragma unroll
        for (int u = 0; u < 5; ++u) {
            int idx = u*32 + t;
            v[u] = (idx < cnt) ? scand[idx] : U64MAX;
        }
        for (int r = 0; r < KNN; ++r) {
            unsigned long long mm = U64MAX;
            #pragma unroll
            for (int u = 0; u < 5; ++u) mm = umin64(mm, v[u]);
            #pragma unroll
            for (int o = 16; o; o >>= 1) {
                unsigned long long s = __shfl_xor_sync(0xffffffffu, mm, o);
                mm = umin64(mm, s);
            }
            #pragma unroll
            for (int u = 0; u < 5; ++u) if (v[u] == mm) v[u] = U64MAX;
            if (t == 0) g_knn[i*KNN + r] = (int)(mm & 0xFFFFFFFFu);
        }
    }
}

// count original edges per row/col (for CSR/CSC of S)
__global__ void k_count(const long long* __restrict__ e64,
                        const int* __restrict__ e32, int E) {
    int is64 = g_is64;
    int e = blockIdx.x * blockDim.x + threadIdx.x;
    if (e >= E) return;
    int r, c; edge_rc(e64, e32, E, is64, e, r, c);
    atomicAdd(&g_rowcnt[r], 1);
    atomicAdd(&g_colcnt[c], 1);
}

// exclusive scan: block 0 rows (+xfill = rowptr + 15*i), block 1 cols
__global__ void k_scan() {
    int isrow = (blockIdx.x == 0);
    const int* cnt = isrow ? g_rowcnt : g_colcnt;
    int* ptr  = isrow ? g_rowptr  : g_colptr;
    int* fill = isrow ? g_rowfill : g_colfill;
    __shared__ int sh[1024];
    int t = threadIdx.x;
    int v[4]; int s = 0;
    #pragma unroll
    for (int k = 0; k < 4; ++k) { v[k] = cnt[t*4 + k]; s += v[k]; }
    sh[t] = s;
    __syncthreads();
    for (int d = 1; d < 1024; d <<= 1) {
        int add = (t >= d) ? sh[t - d] : 0;
        __syncthreads();
        sh[t] += add;
        __syncthreads();
    }
    int excl = sh[t] - s;
    #pragma unroll
    for (int k = 0; k < 4; ++k) {
        int idx = t*4 + k;
        ptr[idx] = excl; fill[idx] = excl;
        if (isrow) g_xfill[idx] = excl + KNN*idx;
        excl += v[k];
    }
    if (t == 1023) ptr[Nn] = excl;
}

// scatter extended adjacency (orig edges + kNN) into xcols
__global__ void k_xscatter(const long long* __restrict__ e64,
                           const int* __restrict__ e32, int E) {
    int is64 = g_is64;
    int t = blockIdx.x * blockDim.x + threadIdx.x;
    if (t < E) {
        int r, c; edge_rc(e64, e32, E, is64, t, r, c);
        int p = atomicAdd(&g_xfill[r], 1);
        g_xcols[p] = c;
    } else if (t < E + NK) {
        int ke = t - E;
        int r = ke / KNN;
        int p = atomicAdd(&g_xfill[r], 1);
        g_xcols[p] = g_knn[ke] & NMASK;
    }
}

// per-node per-feature min of y over extended neighbors (gather, no atomics)
__global__ void k_min() {
    __shared__ float red[256];
    int i = blockIdx.x, t = threadIdx.x;
    int f = t & 63, c = t >> 6;
    int x0 = g_rowptr[i]   + KNN * i;
    int x1 = g_rowptr[i+1] + KNN * (i+1);
    float m = FLT_MAX;
    for (int p = x0 + c; p < x1; p += 4) {
        int col = g_xcols[p];
        m = fminf(m, g_y[col*Hh + f]);
    }
    red[t] = m;
    __syncthreads();
    if (t < 128) red[t] = fminf(red[t], red[t + 128]);
    __syncthreads();
    if (t < 64) g_minv[i*Hh + t] = fminf(red[t], red[t + 64]);
}

// feats = (y + b_theta - min) @ W_phi^T + b_phi      (32 rows/block)
__global__ void k_feats(const float* __restrict__ bth,
                        const float* __restrict__ Wphi,
                        const float* __restrict__ bphi) {
    __shared__ float sWt[Hh*Hh];
    __shared__ float sA[32*Hh];
    int t = threadIdx.x;
    int r0 = blockIdx.x * 32;
    for (int idx = t; idx < Hh*Hh; idx += 256) {
        int f = idx >> 6, h = idx & 63;
        sWt[h*Hh + f] = Wphi[idx];
    }
    for (int idx = t; idx < 32*Hh; idx += 256) {
        int f = idx & 63;
        int gi = r0*Hh + idx;
        sA[idx] = g_y[gi] + bth[f] - g_minv[gi];
    }
    __syncthreads();
    for (int o = t; o < 32*Hh; o += 256) {
        int li = o >> 6, f = o & 63;
        float acc = bphi[f];
        #pragma unroll
        for (int h = 0; h < Hh; ++h) acc += sA[li*Hh + h] * sWt[h*Hh + f];
        g_feats[r0*Hh + o] = acc;
    }
}

// q = feats @ W_q^T,  k = feats @ W_k^T
__global__ void k_qk(const float* __restrict__ Wq, const float* __restrict__ Wk) {
    __shared__ float sWq[Hh*Hh];
    __shared__ float sWk[Hh*Hh];
    __shared__ float sF[32*Hh];
    int t = threadIdx.x;
    int r0 = blockIdx.x * 32;
    for (int idx = t; idx < Hh*Hh; idx += 256) {
        int f = idx >> 6, h = idx & 63;
        sWq[h*Hh + f] = Wq[idx];
        sWk[h*Hh + f] = Wk[idx];
    }
    for (int idx = t; idx < 32*Hh; idx += 256) sF[idx] = g_feats[r0*Hh + idx];
    __syncthreads();
    for (int o = t; o < 32*Hh; o += 256) {
        int li = o >> 6, f = o & 63;
        float aq = 0.0f, ak = 0.0f;
        #pragma unroll
        for (int h = 0; h < Hh; ++h) {
            float fv = sF[li*Hh + h];
            aq += fv * sWq[h*Hh + f];
            ak += fv * sWk[h*Hh + f];
        }
        g_q[r0*Hh + o] = aq;
        g_k[r0*Hh + o] = ak;
    }
}

// attn[e] = dot(q[row], k[col]) scattered RAW into CSR slot. warp/edge.
__global__ void k_attn(const long long* __restrict__ e64,
                       const int* __restrict__ e32, int E) {
    int is64 = g_is64;
    int w = (blockIdx.x * blockDim.x + threadIdx.x) >> 5;
    int lane = threadIdx.x & 31;
    if (w >= E) return;
    int row, col;
    edge_rc(e64, e32, E, is64, w, row, col);
    float a = g_q[row*Hh + lane]      * g_k[col*Hh + lane]
            + g_q[row*Hh + 32 + lane] * g_k[col*Hh + 32 + lane];
    #pragma unroll
    for (int o = 16; o; o >>= 1) a += __shfl_xor_sync(0xffffffffu, a, o);
    if (lane == 0) {
        int p = atomicAdd(&g_rowfill[row], 1);
        g_rowpack[p] = ((unsigned long long)__float_as_uint(a) << 32) | (unsigned)col;
    }
}

// per-row softmax over CSR entries (warp/row), normalize in place + emit CSC
__global__ void k_softmax() {
    int w = (blockIdx.x * blockDim.x + threadIdx.x) >> 5;   // row index
    int lane = threadIdx.x & 31;
    if (w >= Nn) return;
    int r0 = g_rowptr[w], r1 = g_rowptr[w+1];
    if (r0 == r1) return;

    float m = -FLT_MAX;
    for (int e = r0 + lane; e < r1; e += 32)
        m = fmaxf(m, __uint_as_float((unsigned)(g_rowpack[e] >> 32)));
    #pragma unroll
    for (int o = 16; o; o >>= 1)
        m = fmaxf(m, __shfl_xor_sync(0xffffffffu, m, o));

    float s = 0.0f;
    for (int e = r0 + lane; e < r1; e += 32)
        s += expf(__uint_as_float((unsigned)(g_rowpack[e] >> 32)) - m);
    #pragma unroll
    for (int o = 16; o; o >>= 1)
        s += __shfl_xor_sync(0xffffffffu, s, o);
    float inv = 1.0f / s;

    for (int e = r0 + lane; e < r1; e += 32) {
        unsigned long long pk = g_rowpack[e];
        int col = (int)(pk & 0xFFFFFFFFu);
        float v = expf(__uint_as_float((unsigned)(pk >> 32)) - m) * inv;
        unsigned long long pv = ((unsigned long long)__float_as_uint(v)) << 32;
        g_rowpack[e] = pv | (unsigned)col;
        int c = atomicAdd(&g_colfill[col], 1);
        g_cscpack[c] = pv | (unsigned)w;
    }
}

// A_s row i: 512 threads, warp per S-entry p, lane per A-entry qq (champion)
__global__ void k_out(float* __restrict__ out) {
    __shared__ float orow[Nn];   // 16 KB
    int i = blockIdx.x, t = threadIdx.x;
    int lane = t & 31, w = t >> 5;               // 16 warps
    for (int j = t; j < Nn; j += 512) orow[j] = 0.0f;
    __syncthreads();
    int r0 = g_rowptr[i], r1 = g_rowptr[i+1];
    for (int p = r0 + w; p < r1; p += 16) {
        unsigned long long pk = g_rowpack[p];
        int k = (int)(pk & 0xFFFFFFFFu);
        float s = __uint_as_float((unsigned)(pk >> 32));
        int a0 = g_rowptr[k], a1 = g_rowptr[k+1];
        for (int qq = a0 + lane; qq < a1; qq += 32) {
            int l = (int)(g_rowpack[qq] & 0xFFFFFFFFu);
            int c0 = g_colptr[l], c1 = g_colptr[l+1];
            for (int r = c0; r < c1; ++r) {
                unsigned long long ck = g_cscpack[r];
                atomicAdd(&orow[(unsigned)(ck & 0xFFFFFFFFu)],
                          s * __uint_as_float((unsigned)(ck >> 32)));
            }
        }
    }
    __syncthreads();
    float4* o4 = (float4*)(out + (size_t)i * Nn);
    for (int j = t; j < Nn/4; j += 512)
        o4[j] = make_float4(orow[4*j], orow[4*j+1], orow[4*j+2], orow[4*j+3]);
}

// ---------------- launch ----------------
extern "C" void kernel_launch(void* const* d_in, const int* in_sizes, int n_in,
                              void* d_out, int out_size) {
    const float* x    = (const float*)d_in[0];
    const void*  ei   = d_in[1];
    const float* Wth  = (const float*)d_in[2];
    const float* bth  = (const float*)d_in[3];
    const float* Wphi = (const float*)d_in[4];
    const float* bphi = (const float*)d_in[5];
    const float* Wq   = (const float*)d_in[6];
    const float* Wk   = (const float*)d_in[7];
    float* out = (float*)d_out;

    int E = in_sizes[1] / 2;
    const long long* e64 = (const long long*)ei;
    const int*       e32 = (const int*)ei;

    k_initdetect<<<16, 256>>>((const unsigned long long*)ei);
    k_y<<<(Nn*Hh + 255)/256, 256>>>(x, Wth);
    k_knn<<<Nn, 256>>>();
    k_count<<<(E + 255)/256, 256>>>(e64, e32, E);
    k_scan<<<2, 1024>>>();
    k_xscatter<<<(E + NK + 255)/256, 256>>>(e64, e32, E);
    k_min<<<Nn, 256>>>();
    k_feats<<<Nn/32, 256>>>(bth, Wphi, bphi);
    k_qk<<<Nn/32, 256>>>(Wq, Wk);
    k_attn<<<(E*32 + 255)/256, 256>>>(e64, e32, E);
    k_softmax<<<(Nn*32 + 255)/256, 256>>>();
    k_out<<<Nn, 512>>>(out);
}

// round 14
// speedup vs baseline: 1.1478x; 1.0055x over previous
#include <cuda_runtime.h>
#include <cstdint>
#include <float.h>

#define Nn    4096
#define NMASK 4095
#define Hh    64
#define KNN   15
#define MAXE  65536
#define NK    (Nn*KNN)
#define XMAX  (MAXE+NK)
#define CAND  160
#define U64MAX 0xFFFFFFFFFFFFFFFFULL

// ---------------- scratch (device globals; no allocs) ----------------
__device__ int      g_is64;
__device__ float4   g_pts[Nn];                  // x,y,z,|x|^2
__device__ float    g_y[Nn*Hh];
__device__ float    g_minv[Nn*Hh];
__device__ float    g_q[Nn*Hh];
__device__ float    g_k[Nn*Hh];
__device__ int      g_knn[NK];
__device__ int      g_rowcnt[Nn];
__device__ int      g_colcnt[Nn];
__device__ int      g_rowptr[Nn+1];
__device__ int      g_colptr[Nn+1];
__device__ int      g_rowfill[Nn];
__device__ int      g_colfill[Nn];
__device__ int      g_xfill[Nn];
__device__ int      g_xcols[XMAX];
__device__ unsigned long long g_rowpack[MAXE];  // (f32bits(val)<<32)|col  CSR of S
__device__ unsigned long long g_cscpack[MAXE];  // (f32bits(val)<<32)|row  CSC of S

// ---------------- helpers ----------------
__device__ __forceinline__ unsigned fenc(float f) {
    unsigned u = __float_as_uint(f);
    return (u & 0x80000000u) ? ~u : (u ^ 0x80000000u);
}
__device__ __forceinline__ float fdec(unsigned e) {
    unsigned u = (e & 0x80000000u) ? (e ^ 0x80000000u) : ~e;
    return __uint_as_float(u);
}
__device__ __forceinline__ void edge_rc(const long long* e64, const int* e32,
                                        int E, int is64, int e, int& r, int& c) {
    if (is64) { r = ((int)e64[e]) & NMASK; c = ((int)e64[E + e]) & NMASK; }
    else      { r = e32[e] & NMASK;        c = e32[E + e] & NMASK; }
}
__device__ __forceinline__ unsigned long long umin64(unsigned long long a,
                                                     unsigned long long b) {
    return a < b ? a : b;
}

// ---------------- kernels ----------------
// y = x @ W_theta^T, g_pts build, counter init, dtype detect — one kernel
__global__ void k_y(const float* __restrict__ x, const float* __restrict__ Wt,
                    const unsigned long long* __restrict__ ei) {
    int t = blockIdx.x * blockDim.x + threadIdx.x;
    if (t == 0) {
        int ok64 = 1;
        for (int i = 0; i < 64; ++i) {
            unsigned long long v = ei[i];
            if ((v >> 32) != 0ULL || (v & 0xFFFFFFFFULL) >= (unsigned)Nn) { ok64 = 0; break; }
        }
        g_is64 = ok64;
    }
    if (t < Nn) { g_rowcnt[t] = 0; g_colcnt[t] = 0; }
    if (t >= Nn * Hh) return;
    int i = t >> 6, f = t & 63;
    float x0 = x[i*3+0], x1 = x[i*3+1], x2 = x[i*3+2];
    g_y[t] = Wt[f*3+0]*x0 + Wt[f*3+1]*x1 + Wt[f*3+2]*x2;
    if (f == 0) g_pts[i] = make_float4(x0, x1, x2, x0*x0 + x1*x1 + x2*x2);
}

// kNN v5 (measured 42.5us): block per query, float4 loads, threshold-then-select.
__global__ void k_knn() {
    __shared__ float smin[256];
    __shared__ unsigned long long scand[CAND];
    __shared__ int scnt;
    __shared__ float sT;
    int i = blockIdx.x, t = threadIdx.x;

    float4 Q = g_pts[i];
    float d2v[16];
    float m = FLT_MAX;
    #pragma unroll
    for (int u = 0; u < 16; ++u) {
        int j = u*256 + t;
        float4 P = g_pts[j];
        float dot = Q.x*P.x + Q.y*P.y + Q.z*P.z;
        float d2  = (Q.w - 2.0f*dot) + P.w;     // matches (sq_i - 2*xy) + sq_j
        if (j == i) d2 = FLT_MAX;
        d2v[u] = d2;
        m = fminf(m, d2);
    }
    smin[t] = m;
    if (t == 0) scnt = 0;
    __syncthreads();

    if (t < 32) {
        unsigned long long v[8];
        #pragma unroll
        for (int u = 0; u < 8; ++u) {
            int idx = u*32 + t;
            v[u] = ((unsigned long long)fenc(smin[idx]) << 32) | (unsigned)idx;
        }
        unsigned long long last = 0;
        for (int r = 0; r < KNN; ++r) {
            unsigned long long mm = U64MAX;
            #pragma unroll
            for (int u = 0; u < 8; ++u) mm = umin64(mm, v[u]);
            #pragma unroll
            for (int o = 16; o; o >>= 1) {
                unsigned long long s = __shfl_xor_sync(0xffffffffu, mm, o);
                mm = umin64(mm, s);
            }
            #pragma unroll
            for (int u = 0; u < 8; ++u) if (v[u] == mm) v[u] = U64MAX;
            last = mm;
        }
        if (t == 0) sT = fdec((unsigned)(last >> 32));
    }
    __syncthreads();

    float T = sT;
    #pragma unroll
    for (int u = 0; u < 16; ++u) {
        if (d2v[u] <= T) {
            int p = atomicAdd(&scnt, 1);
            if (p < CAND)
                scand[p] = ((unsigned long long)fenc(d2v[u]) << 32) | (unsigned)(u*256 + t);
        }
    }
    __syncthreads();

    int cnt = scnt; if (cnt > CAND) cnt = CAND;
    if (cnt == KNN) {
        if (t < KNN) g_knn[i*KNN + t] = (int)(scand[t] & 0xFFFFFFFFu);
    } else if (t < 32) {
        unsigned long long v[5];
        #pragma unroll
        for (int u = 0; u < 5; ++u) {
            int idx = u*32 + t;
            v[u] = (idx < cnt) ? scand[idx] : U64MAX;
        }
        for (int r = 0; r < KNN; ++r) {
            unsigned long long mm = U64MAX;
            #pragma unroll
            for (int u = 0; u < 5; ++u) mm = umin64(mm, v[u]);
            #pragma unroll
            for (int o = 16; o; o >>= 1) {
                unsigned long long s = __shfl_xor_sync(0xffffffffu, mm, o);
                mm = umin64(mm, s);
            }
            #pragma unroll
            for (int u = 0; u < 5; ++u) if (v[u] == mm) v[u] = U64MAX;
            if (t == 0) g_knn[i*KNN + r] = (int)(mm & 0xFFFFFFFFu);
        }
    }
}

// count original edges per row/col (for CSR/CSC of S)
__global__ void k_count(const long long* __restrict__ e64,
                        const int* __restrict__ e32, int E) {
    int is64 = g_is64;
    int e = blockIdx.x * blockDim.x + threadIdx.x;
    if (e >= E) return;
    int r, c; edge_rc(e64, e32, E, is64, e, r, c);
    atomicAdd(&g_rowcnt[r], 1);
    atomicAdd(&g_colcnt[c], 1);
}

// exclusive scan: block 0 rows (+xfill = rowptr + 15*i), block 1 cols
__global__ void k_scan() {
    int isrow = (blockIdx.x == 0);
    const int* cnt = isrow ? g_rowcnt : g_colcnt;
    int* ptr  = isrow ? g_rowptr  : g_colptr;
    int* fill = isrow ? g_rowfill : g_colfill;
    __shared__ int sh[1024];
    int t = threadIdx.x;
    int v[4]; int s = 0;
    #pragma unroll
    for (int k = 0; k < 4; ++k) { v[k] = cnt[t*4 + k]; s += v[k]; }
    sh[t] = s;
    __syncthreads();
    for (int d = 1; d < 1024; d <<= 1) {
        int add = (t >= d) ? sh[t - d] : 0;
        __syncthreads();
        sh[t] += add;
        __syncthreads();
    }
    int excl = sh[t] - s;
    #pragma unroll
    for (int k = 0; k < 4; ++k) {
        int idx = t*4 + k;
        ptr[idx] = excl; fill[idx] = excl;
        if (isrow) g_xfill[idx] = excl + KNN*idx;
        excl += v[k];
    }
    if (t == 1023) ptr[Nn] = excl;
}

// scatter extended adjacency (orig edges + kNN) into xcols
__global__ void k_xscatter(const long long* __restrict__ e64,
                           const int* __restrict__ e32, int E) {
    int is64 = g_is64;
    int t = blockIdx.x * blockDim.x + threadIdx.x;
    if (t < E) {
        int r, c; edge_rc(e64, e32, E, is64, t, r, c);
        int p = atomicAdd(&g_xfill[r], 1);
        g_xcols[p] = c;
    } else if (t < E + NK) {
        int ke = t - E;
        int r = ke / KNN;
        int p = atomicAdd(&g_xfill[r], 1);
        g_xcols[p] = g_knn[ke] & NMASK;
    }
}

// per-node per-feature min of y over extended neighbors (gather, no atomics)
__global__ void k_min() {
    __shared__ float red[256];
    int i = blockIdx.x, t = threadIdx.x;
    int f = t & 63, c = t >> 6;
    int x0 = g_rowptr[i]   + KNN * i;
    int x1 = g_rowptr[i+1] + KNN * (i+1);
    float m = FLT_MAX;
    for (int p = x0 + c; p < x1; p += 4) {
        int col = g_xcols[p];
        m = fminf(m, g_y[col*Hh + f]);
    }
    red[t] = m;
    __syncthreads();
    if (t < 128) red[t] = fminf(red[t], red[t + 128]);
    __syncthreads();
    if (t < 64) g_minv[i*Hh + t] = fminf(red[t], red[t + 64]);
}

// fused: feats = (y + b_theta - min)@Wphi^T + bphi (smem only), then
// q = feats@Wq^T, k = feats@Wk^T. One 16KB weight buffer staged 3x.
__global__ void k_fqk(const float* __restrict__ bth,
                      const float* __restrict__ Wphi,
                      const float* __restrict__ bphi,
                      const float* __restrict__ Wq,
                      const float* __restrict__ Wk) {
    __shared__ float sW[Hh*Hh];     // 16 KB, staged: Wphi -> Wq -> Wk
    __shared__ float sA[32*Hh];     // 8 KB: input rows
    __shared__ float sF[32*Hh];     // 8 KB: feats
    int t = threadIdx.x;
    int r0 = blockIdx.x * 32;

    // stage 1: Wphi (transposed) + input tile
    for (int idx = t; idx < Hh*Hh; idx += 256) {
        int f = idx >> 6, h = idx & 63;
        sW[h*Hh + f] = Wphi[idx];
    }
    for (int idx = t; idx < 32*Hh; idx += 256) {
        int f = idx & 63;
        int gi = r0*Hh + idx;
        sA[idx] = g_y[gi] + bth[f] - g_minv[gi];
    }
    __syncthreads();
    for (int o = t; o < 32*Hh; o += 256) {
        int li = o >> 6, f = o & 63;
        float acc = bphi[f];
        #pragma unroll
        for (int h = 0; h < Hh; ++h) acc += sA[li*Hh + h] * sW[h*Hh + f];
        sF[o] = acc;
    }
    __syncthreads();

    // stage 2: Wq
    for (int idx = t; idx < Hh*Hh; idx += 256) {
        int f = idx >> 6, h = idx & 63;
        sW[h*Hh + f] = Wq[idx];
    }
    __syncthreads();
    for (int o = t; o < 32*Hh; o += 256) {
        int li = o >> 6, f = o & 63;
        float acc = 0.0f;
        #pragma unroll
        for (int h = 0; h < Hh; ++h) acc += sF[li*Hh + h] * sW[h*Hh + f];
        g_q[r0*Hh + o] = acc;
    }
    __syncthreads();

    // stage 3: Wk
    for (int idx = t; idx < Hh*Hh; idx += 256) {
        int f = idx >> 6, h = idx & 63;
        sW[h*Hh + f] = Wk[idx];
    }
    __syncthreads();
    for (int o = t; o < 32*Hh; o += 256) {
        int li = o >> 6, f = o & 63;
        float acc = 0.0f;
        #pragma unroll
        for (int h = 0; h < Hh; ++h) acc += sF[li*Hh + h] * sW[h*Hh + f];
        g_k[r0*Hh + o] = acc;
    }
}

// attn[e] = dot(q[row], k[col]) scattered RAW into CSR slot. warp/edge.
__global__ void k_attn(const long long* __restrict__ e64,
                       const int* __restrict__ e32, int E) {
    int is64 = g_is64;
    int w = (blockIdx.x * blockDim.x + threadIdx.x) >> 5;
    int lane = threadIdx.x & 31;
    if (w >= E) return;
    int row, col;
    edge_rc(e64, e32, E, is64, w, row, col);
    float a = g_q[row*Hh + lane]      * g_k[col*Hh + lane]
            + g_q[row*Hh + 32 + lane] * g_k[col*Hh + 32 + lane];
    #pragma unroll
    for (int o = 16; o; o >>= 1) a += __shfl_xor_sync(0xffffffffu, a, o);
    if (lane == 0) {
        int p = atomicAdd(&g_rowfill[row], 1);
        g_rowpack[p] = ((unsigned long long)__float_as_uint(a) << 32) | (unsigned)col;
    }
}

// per-row softmax over CSR entries (warp/row), normalize in place + emit CSC
__global__ void k_softmax() {
    int w = (blockIdx.x * blockDim.x + threadIdx.x) >> 5;   // row index
    int lane = threadIdx.x & 31;
    if (w >= Nn) return;
    int r0 = g_rowptr[w], r1 = g_rowptr[w+1];
    if (r0 == r1) return;

    float m = -FLT_MAX;
    for (int e = r0 + lane; e < r1; e += 32)
        m = fmaxf(m, __uint_as_float((unsigned)(g_rowpack[e] >> 32)));
    #pragma unroll
    for (int o = 16; o; o >>= 1)
        m = fmaxf(m, __shfl_xor_sync(0xffffffffu, m, o));

    float s = 0.0f;
    for (int e = r0 + lane; e < r1; e += 32)
        s += expf(__uint_as_float((unsigned)(g_rowpack[e] >> 32)) - m);
    #pragma unroll
    for (int o = 16; o; o >>= 1)
        s += __shfl_xor_sync(0xffffffffu, s, o);
    float inv = 1.0f / s;

    for (int e = r0 + lane; e < r1; e += 32) {
        unsigned long long pk = g_rowpack[e];
        int col = (int)(pk & 0xFFFFFFFFu);
        float v = expf(__uint_as_float((unsigned)(pk >> 32)) - m) * inv;
        unsigned long long pv = ((unsigned long long)__float_as_uint(v)) << 32;
        g_rowpack[e] = pv | (unsigned)col;
        int c = atomicAdd(&g_colfill[col], 1);
        g_cscpack[c] = pv | (unsigned)w;
    }
}

// A_s row i: 512 threads, warp per S-entry p, lane per A-entry qq (champion)
__global__ void k_out(float* __restrict__ out) {
    __shared__ float orow[Nn];   // 16 KB
    int i = blockIdx.x, t = threadIdx.x;
    int lane = t & 31, w = t >> 5;               // 16 warps
    for (int j = t; j < Nn; j += 512) orow[j] = 0.0f;
    __syncthreads();
    int r0 = g_rowptr[i], r1 = g_rowptr[i+1];
    for (int p = r0 + w; p < r1; p += 16) {
        unsigned long long pk = g_rowpack[p];
        int k = (int)(pk & 0xFFFFFFFFu);
        float s = __uint_as_float((unsigned)(pk >> 32));
        int a0 = g_rowptr[k], a1 = g_rowptr[k+1];
        for (int qq = a0 + lane; qq < a1; qq += 32) {
            int l = (int)(g_rowpack[qq] & 0xFFFFFFFFu);
            int c0 = g_colptr[l], c1 = g_colptr[l+1];
            for (int r = c0; r < c1; ++r) {
                unsigned long long ck = g_cscpack[r];
                atomicAdd(&orow[(unsigned)(ck & 0xFFFFFFFFu)],
                          s * __uint_as_float((unsigned)(ck >> 32)));
            }
        }
    }
    __syncthreads();
    float4* o4 = (float4*)(out + (size_t)i * Nn);
    for (int j = t; j < Nn/4; j += 512)
        o4[j] = make_float4(orow[4*j], orow[4*j+1], orow[4*j+2], orow[4*j+3]);
}

// ---------------- launch ----------------
extern "C" void kernel_launch(void* const* d_in, const int* in_sizes, int n_in,
                              void* d_out, int out_size) {
    const float* x    = (const float*)d_in[0];
    const void*  ei   = d_in[1];
    const float* Wth  = (const float*)d_in[2];
    const float* bth  = (const float*)d_in[3];
    const float* Wphi = (const float*)d_in[4];
    const float* bphi = (const float*)d_in[5];
    const float* Wq   = (const float*)d_in[6];
    const float* Wk   = (const float*)d_in[7];
    float* out = (float*)d_out;

    int E = in_sizes[1] / 2;
    const long long* e64 = (const long long*)ei;
    const int*       e32 = (const int*)ei;

    k_y<<<(Nn*Hh + 255)/256, 256>>>(x, Wth, (const unsigned long long*)ei);
    k_knn<<<Nn, 256>>>();
    k_count<<<(E + 255)/256, 256>>>(e64, e32, E);
    k_scan<<<2, 1024>>>();
    k_xscatter<<<(E + NK + 255)/256, 256>>>(e64, e32, E);
    k_min<<<Nn, 256>>>();
    k_fqk<<<Nn/32, 256>>>(bth, Wphi, bphi, Wq, Wk);
    k_attn<<<(E*32 + 255)/256, 256>>>(e64, e32, E);
    k_softmax<<<(Nn*32 + 255)/256, 256>>>();
    k_out<<<Nn, 512>>>(out);
}